// round 2
// baseline (speedup 1.0000x reference)
#include <cuda_runtime.h>
#include <stdint.h>

#define EMB 768
#define VEC (EMB / 4)   // 192 float4 per row

// Flag: 1 => indices are int32, 0 => indices are int64 (little-endian, high word 0)
__device__ int g_idx_is_i32;

// Single-block detection kernel. Reads the first n_words 32-bit words of the
// index buffer (n_words == token count, so always within the buffer for
// either dtype). If storage is int64, every odd word is the high half of a
// value in [0, 50257) => zero. If storage is int32, odd words are random
// indices and are (with overwhelming certainty) not all zero.
__global__ void detect_idx_dtype(const unsigned int* __restrict__ w, int n_words) {
    __shared__ unsigned int s_acc;
    if (threadIdx.x == 0) s_acc = 0u;
    __syncthreads();

    unsigned int acc = 0u;
    for (int i = 1 + 2 * threadIdx.x; i < n_words; i += 2 * blockDim.x)
        acc |= w[i];

    // warp reduce then shared OR
    #pragma unroll
    for (int off = 16; off > 0; off >>= 1)
        acc |= __shfl_down_sync(0xFFFFFFFFu, acc, off);
    if ((threadIdx.x & 31) == 0 && acc)
        atomicOr(&s_acc, acc);
    __syncthreads();

    if (threadIdx.x == 0)
        g_idx_is_i32 = (s_acc != 0u) ? 1 : 0;
}

// One float4 per thread. token = gid / VEC, lane = gid % VEC.
// Each warp's 32 lanes fall inside (at most two) tokens, so the index load is
// broadcast/coalesced and the table read is a contiguous 128B+ stream per row.
__global__ void __launch_bounds__(256)
embedding_gather(const void* __restrict__ idx_raw,
                 const float4* __restrict__ table,
                 float4* __restrict__ out,
                 int n_tokens) {
    long long gid = (long long)blockIdx.x * blockDim.x + threadIdx.x;
    long long total = (long long)n_tokens * VEC;
    if (gid >= total) return;

    int token = (int)(gid / VEC);
    int lane  = (int)(gid % VEC);

    long long idx;
    if (g_idx_is_i32) {
        idx = (long long)__ldg((const int*)idx_raw + token);
    } else {
        idx = __ldg((const long long*)idx_raw + token);
    }

    out[gid] = __ldg(table + idx * VEC + lane);
}

extern "C" void kernel_launch(void* const* d_in, const int* in_sizes, int n_in,
                              void* d_out, int out_size) {
    // indices buffer is the small one; table is 50257*768 elements.
    const void* d_idx;
    const void* d_table;
    int n_tokens;
    if (in_sizes[0] < in_sizes[1]) {
        d_idx = d_in[0];  d_table = d_in[1];  n_tokens = in_sizes[0];
    } else {
        d_idx = d_in[1];  d_table = d_in[0];  n_tokens = in_sizes[1];
    }

    detect_idx_dtype<<<1, 1024>>>((const unsigned int*)d_idx, n_tokens);

    long long total_vec = (long long)n_tokens * VEC;
    int threads = 256;
    int blocks = (int)((total_vec + threads - 1) / threads);
    embedding_gather<<<blocks, threads>>>(d_idx,
                                          (const float4*)d_table,
                                          (float4*)d_out,
                                          n_tokens);
}

// round 3
// speedup vs baseline: 1.4147x; 1.4147x over previous
#include <cuda_runtime.h>
#include <stdint.h>

#define EMB 768
#define VEC (EMB / 4)        // 192 float4 per row
#define F4_PER_LANE (VEC / 32)  // 6
#define WARPS_PER_BLOCK 8
#define THREADS (WARPS_PER_BLOCK * 32)

// Warp-per-token gather. Lane l handles float4 elements {l, l+32, ..., l+160}
// of the row: 6 independent LDG.128 then 6 STG.128 (streaming) per lane.
// Index dtype (int32 vs int64) is detected per-block from the odd 32-bit
// words of the index buffer: int64 storage => all high halves zero;
// int32 storage => 127 random vocab indices all zero has prob ~(1/50257)^127.
__global__ void __launch_bounds__(THREADS)
embedding_gather(const void* __restrict__ idx_raw,
                 const float4* __restrict__ table,
                 float4* __restrict__ out,
                 int n_tokens) {
    // ---- per-block dtype detection (1 KB coalesced read, L2-hot) ----
    const unsigned int* w = (const unsigned int*)idx_raw;
    unsigned int probe = 0u;
    int widx = 2 * threadIdx.x + 1;
    if (threadIdx.x < 128 && widx < n_tokens)
        probe = w[widx];
    int idx_is_i32 = __syncthreads_or(probe != 0u);

    int warp = (blockIdx.x * WARPS_PER_BLOCK) + (threadIdx.x >> 5);
    int lane = threadIdx.x & 31;
    if (warp >= n_tokens) return;

    long long idx;
    if (idx_is_i32) {
        idx = (long long)__ldg((const int*)idx_raw + warp);
    } else {
        idx = __ldg((const long long*)idx_raw + warp);
    }

    const float4* __restrict__ src = table + idx * VEC + lane;
    float4* __restrict__ dst = out + (long long)warp * VEC + lane;

    float4 v[F4_PER_LANE];
    #pragma unroll
    for (int j = 0; j < F4_PER_LANE; j++)
        v[j] = __ldg(src + 32 * j);

    #pragma unroll
    for (int j = 0; j < F4_PER_LANE; j++)
        __stwt(dst + 32 * j, v[j]);
}

extern "C" void kernel_launch(void* const* d_in, const int* in_sizes, int n_in,
                              void* d_out, int out_size) {
    // indices buffer is the small one; table is 50257*768 elements.
    const void* d_idx;
    const void* d_table;
    int n_tokens;
    if (in_sizes[0] < in_sizes[1]) {
        d_idx = d_in[0];  d_table = d_in[1];  n_tokens = in_sizes[0];
    } else {
        d_idx = d_in[1];  d_table = d_in[0];  n_tokens = in_sizes[1];
    }

    int blocks = (n_tokens + WARPS_PER_BLOCK - 1) / WARPS_PER_BLOCK;
    embedding_gather<<<blocks, THREADS>>>(d_idx,
                                          (const float4*)d_table,
                                          (float4*)d_out,
                                          n_tokens);
}